// round 12
// baseline (speedup 1.0000x reference)
#include <cuda_runtime.h>
#include <math.h>

// ---------------- problem constants ----------------
#define S_LEN   257
#define BATCH   8
#define TOK     (S_LEN * BATCH)      // 2056
#define DMODEL  1024
#define NHEAD   16
#define DHEAD   64
#define FFDIM   4096
#define NLAYER  24
#define VOCAB   16384
#define CLIPD   512
#define SEQ_OUT 256                          // S-1
#define LOGITS_ELEMS ((size_t)BATCH * SEQ_OUT * VOCAB)   // 33,554,432

// ---------------- scratch (__device__ globals: allocation-free) ----------------
__device__ float g_x0  [TOK * DMODEL];
__device__ float g_qkv [TOK * 3 * DMODEL];
__device__ float g_ctx [TOK * DMODEL];
__device__ float g_tmp [TOK * DMODEL];
__device__ float g_xmid[TOK * DMODEL];
__device__ float g_ff  [TOK * FFDIM];

// ---------------- GEMM: C[M,N] = A[M,K] @ B[N,K]^T + bias, fp32 ----------------
// mode 0: plain   mode 1: exact gelu   mode 2: logits store (transpose to [B,S-1,V])
#define BM 128
#define BN 128
#define BK 16

__global__ __launch_bounds__(256) void gemm_nt(
    const float* __restrict__ A, const float* __restrict__ B,
    const float* __restrict__ bias, float* __restrict__ C,
    int M, int N, int K, int mode)
{
    __shared__ __align__(16) float As[BK][BM + 4];
    __shared__ __align__(16) float Bs[BK][BN + 4];

    const int tid = threadIdx.x;
    const int tx = tid & 15;          // 16 col groups
    const int ty = tid >> 4;          // 16 row groups
    const int mBase = blockIdx.y * BM;
    const int nBase = blockIdx.x * BN;

    float acc[8][8];
#pragma unroll
    for (int i = 0; i < 8; i++)
#pragma unroll
        for (int j = 0; j < 8; j++) acc[i][j] = 0.f;

    for (int kt = 0; kt < K; kt += BK) {
        // load A tile (BMxBK) transposed into As[k][m], bounds-guarded on rows
#pragma unroll
        for (int it = 0; it < 2; it++) {
            int i   = tid + it * 256;
            int row = i >> 2;
            int kc  = (i & 3) << 2;
            float4 v = make_float4(0.f, 0.f, 0.f, 0.f);
            int gr = mBase + row;
            if (gr < M) v = *(const float4*)(A + (size_t)gr * K + kt + kc);
            As[kc + 0][row] = v.x; As[kc + 1][row] = v.y;
            As[kc + 2][row] = v.z; As[kc + 3][row] = v.w;
        }
        // load B tile (BNxBK) transposed into Bs[k][n] (N always multiple of BN)
#pragma unroll
        for (int it = 0; it < 2; it++) {
            int i   = tid + it * 256;
            int row = i >> 2;
            int kc  = (i & 3) << 2;
            float4 v = *(const float4*)(B + (size_t)(nBase + row) * K + kt + kc);
            Bs[kc + 0][row] = v.x; Bs[kc + 1][row] = v.y;
            Bs[kc + 2][row] = v.z; Bs[kc + 3][row] = v.w;
        }
        __syncthreads();

#pragma unroll
        for (int k = 0; k < BK; k++) {
            float ra[8], rb[8];
            *(float4*)&ra[0] = *(const float4*)&As[k][ty * 8];
            *(float4*)&ra[4] = *(const float4*)&As[k][ty * 8 + 4];
            *(float4*)&rb[0] = *(const float4*)&Bs[k][tx * 8];
            *(float4*)&rb[4] = *(const float4*)&Bs[k][tx * 8 + 4];
#pragma unroll
            for (int i = 0; i < 8; i++)
#pragma unroll
                for (int j = 0; j < 8; j++)
                    acc[i][j] = fmaf(ra[i], rb[j], acc[i][j]);
        }
        __syncthreads();
    }

    // epilogue
#pragma unroll
    for (int i = 0; i < 8; i++) {
        int r = mBase + ty * 8 + i;
        if (r < M) {
#pragma unroll
            for (int j = 0; j < 8; j++) {
                int c = nBase + tx * 8 + j;
                float v = acc[i][j] + bias[c];
                if (mode == 1)
                    v = 0.5f * v * (1.0f + erff(v * 0.70710678118654752f));
                if (mode == 2) {
                    // row r of the [2048,V] matrix is token (s = r/8 + 1, b = r%8)
                    C[(size_t)(r & 7) * ((size_t)SEQ_OUT * VOCAB)
                      + (size_t)(r >> 3) * VOCAB + c] = v;
                } else {
                    C[(size_t)r * N + c] = v;
                }
            }
        }
    }
}

// ---------------- residual + LayerNorm: out = LN(x + a) * g + b ----------------
__global__ __launch_bounds__(256) void ln_res(
    const float* __restrict__ x, const float* __restrict__ a,
    const float* __restrict__ g, const float* __restrict__ bt,
    float* __restrict__ out)
{
    const int t = blockIdx.x;
    const int i = threadIdx.x;                // 256 threads * float4 = 1024
    const float4* x4 = (const float4*)(x + (size_t)t * DMODEL);
    const float4* a4 = (const float4*)(a + (size_t)t * DMODEL);
    float4 v = x4[i], av = a4[i];
    v.x += av.x; v.y += av.y; v.z += av.z; v.w += av.w;
    float s = v.x + v.y + v.z + v.w;
    float q = v.x * v.x + v.y * v.y + v.z * v.z + v.w * v.w;

    __shared__ float shs[8], shq[8];
    const int lane = i & 31, w = i >> 5;
#pragma unroll
    for (int o = 16; o; o >>= 1) {
        s += __shfl_xor_sync(0xffffffffu, s, o);
        q += __shfl_xor_sync(0xffffffffu, q, o);
    }
    if (lane == 0) { shs[w] = s; shq[w] = q; }
    __syncthreads();
    if (i < 32) {
        s = (lane < 8) ? shs[lane] : 0.f;
        q = (lane < 8) ? shq[lane] : 0.f;
#pragma unroll
        for (int o = 4; o; o >>= 1) {
            s += __shfl_xor_sync(0xffffffffu, s, o);
            q += __shfl_xor_sync(0xffffffffu, q, o);
        }
        if (lane == 0) { shs[0] = s; shq[0] = q; }
    }
    __syncthreads();
    const float mean = shs[0] * (1.0f / DMODEL);
    const float var  = shq[0] * (1.0f / DMODEL) - mean * mean;
    const float rstd = rsqrtf(var + 1e-5f);

    float4 g4 = ((const float4*)g)[i];
    float4 b4 = ((const float4*)bt)[i];
    float4 o4;
    o4.x = (v.x - mean) * rstd * g4.x + b4.x;
    o4.y = (v.y - mean) * rstd * g4.y + b4.y;
    o4.z = (v.z - mean) * rstd * g4.z + b4.z;
    o4.w = (v.w - mean) * rstd * g4.w + b4.w;
    ((float4*)(out + (size_t)t * DMODEL))[i] = o4;
}

// ---------------- attention: one block per (b,h), K/V staged in smem ----------------
#define KVSTRIDE 68   // 68 % 32 == 4: conflict-free for both passes, 16B-aligned rows
#define ATTN_SMEM ((2 * S_LEN * KVSTRIDE + 8 * DHEAD + 8 * S_LEN) * 4)

__global__ __launch_bounds__(256) void attn_kernel(
    const float* __restrict__ qkv, float* __restrict__ ctx)
{
    extern __shared__ float sm[];
    float* Ks = sm;                                   // S_LEN * 68
    float* Vs = Ks + S_LEN * KVSTRIDE;                // S_LEN * 68
    float* Qs = Vs + S_LEN * KVSTRIDE;                // 8 * 64
    float* Pr = Qs + 8 * DHEAD;                       // 8 * 257

    const int b = blockIdx.x >> 4;
    const int h = blockIdx.x & 15;
    const int tid = threadIdx.x;

    for (int i = tid; i < S_LEN * DHEAD; i += 256) {
        int s = i >> 6, d = i & 63;
        size_t base = (size_t)(s * BATCH + b) * (3 * DMODEL) + h * DHEAD + d;
        Ks[s * KVSTRIDE + d] = qkv[base + DMODEL];
        Vs[s * KVSTRIDE + d] = qkv[base + 2 * DMODEL];
    }
    __syncthreads();

    const int w = tid >> 5, lane = tid & 31;
    float* prw = Pr + w * S_LEN;
    const float4* qr = (const float4*)(Qs + w * DHEAD);

    for (int s = w; s < S_LEN; s += 8) {
        const float* qp = qkv + (size_t)(s * BATCH + b) * (3 * DMODEL) + h * DHEAD;
        Qs[w * DHEAD + lane]      = qp[lane];
        Qs[w * DHEAD + 32 + lane] = qp[32 + lane];
        __syncwarp();

        // causal mask; quirk: mask[0,1] = 0  ->  allowed t = 0..max(s,1)
        const int nt = (s == 0) ? 2 : (s + 1);

        float lmax = -1e30f;
        for (int t = lane; t < nt; t += 32) {
            const float4* kr = (const float4*)(Ks + t * KVSTRIDE);
            float sc = 0.f;
#pragma unroll
            for (int d4 = 0; d4 < 16; d4++) {
                float4 kv = kr[d4], qv = qr[d4];
                sc += qv.x * kv.x + qv.y * kv.y + qv.z * kv.z + qv.w * kv.w;
            }
            sc *= 0.125f;                 // 1/sqrt(64)
            prw[t] = sc;
            lmax = fmaxf(lmax, sc);
        }
#pragma unroll
        for (int o = 16; o; o >>= 1)
            lmax = fmaxf(lmax, __shfl_xor_sync(0xffffffffu, lmax, o));

        float lsum = 0.f;
        for (int t = lane; t < nt; t += 32) {
            float p = expf(prw[t] - lmax);
            prw[t] = p;
            lsum += p;
        }
#pragma unroll
        for (int o = 16; o; o >>= 1)
            lsum += __shfl_xor_sync(0xffffffffu, lsum, o);
        __syncwarp();

        const float inv = 1.0f / lsum;
        float a0 = 0.f, a1 = 0.f;
        for (int t = 0; t < nt; t++) {
            float p = prw[t];
            a0 += p * Vs[t * KVSTRIDE + lane];
            a1 += p * Vs[t * KVSTRIDE + 32 + lane];
        }
        float* cp = ctx + (size_t)(s * BATCH + b) * DMODEL + h * DHEAD;
        cp[lane]      = a0 * inv;
        cp[32 + lane] = a1 * inv;
        __syncwarp();
    }
}

// ---------------- embedding: x0[s,b,:] = prefix/token embed + pos_emb[s] ----------------
__global__ __launch_bounds__(256) void embed_kernel(
    const float* __restrict__ clip_embed, const float* __restrict__ clip_score,
    const int* __restrict__ tokens,
    const float* __restrict__ clip_in_w, const float* __restrict__ score_in_w,
    const float* __restrict__ in_embed, const float* __restrict__ pos_emb,
    float* __restrict__ x0)
{
    const int s = blockIdx.x;       // 0..256
    const int b = blockIdx.y;       // 0..7
    const int tid = threadIdx.x;    // 256
    float* outp = x0 + (size_t)(s * BATCH + b) * DMODEL;
    const float* pe = pos_emb + (size_t)s * DMODEL;

    if (s == 0) {
        __shared__ float ce[CLIPD];
        __shared__ float red[8];
        float ss = 0.f;
        for (int i = tid; i < CLIPD; i += 256) {
            float vv = clip_embed[b * CLIPD + i];
            ce[i] = vv;
            ss += vv * vv;
        }
        const int lane = tid & 31, w = tid >> 5;
#pragma unroll
        for (int o = 16; o; o >>= 1) ss += __shfl_xor_sync(0xffffffffu, ss, o);
        if (lane == 0) red[w] = ss;
        __syncthreads();
        if (tid == 0) {
            float tot = 0.f;
            for (int k = 0; k < 8; k++) tot += red[k];
            red[0] = tot;
        }
        __syncthreads();
        const float scale = sqrtf((float)CLIPD) / fmaxf(sqrtf(red[0]), 1e-12f);
        for (int d = tid; d < DMODEL; d += 256) {
            const float* wr = clip_in_w + (size_t)d * CLIPD;
            float acc = 0.f;
#pragma unroll 4
            for (int c = 0; c < CLIPD; c++) acc += ce[c] * wr[c];
            outp[d] = acc * scale + pe[d];
        }
    } else if (s == 1) {
        const float cs = clip_score[b];
        for (int d = tid; d < DMODEL; d += 256)
            outp[d] = cs * score_in_w[d] + pe[d];
    } else {
        const int tk = tokens[b * (S_LEN - 2) + (s - 2)];
        const float* er = in_embed + (size_t)tk * DMODEL;
        for (int d = tid; d < DMODEL; d += 256)
            outp[d] = er[d] + pe[d];
    }
}

// ---------------- host launcher ----------------
extern "C" void kernel_launch(void* const* d_in, const int* in_sizes, int n_in,
                              void* d_out, int out_size)
{
    const float* clip_embed   = (const float*)d_in[0];
    const float* clip_score   = (const float*)d_in[1];
    const int*   input_tokens = (const int*)  d_in[2];
    const float* clip_in_w    = (const float*)d_in[3];
    const float* score_in_w   = (const float*)d_in[4];
    const float* in_embed     = (const float*)d_in[5];
    const float* pos_emb      = (const float*)d_in[6];
    const float* Wqkv         = (const float*)d_in[7];
    const float* bqkv         = (const float*)d_in[8];
    const float* Wo           = (const float*)d_in[9];
    const float* bo           = (const float*)d_in[10];
    const float* W1           = (const float*)d_in[11];
    const float* b1           = (const float*)d_in[12];
    const float* W2           = (const float*)d_in[13];
    const float* b2           = (const float*)d_in[14];
    const float* ln1_g        = (const float*)d_in[15];
    const float* ln1_b        = (const float*)d_in[16];
    const float* ln2_g        = (const float*)d_in[17];
    const float* ln2_b        = (const float*)d_in[18];
    const float* out_w        = (const float*)d_in[19];
    const float* out_b        = (const float*)d_in[20];

    float* outp  = (float*)d_out;
    float* cache = outp + LOGITS_ELEMS;   // [24, S, B, D] region of d_out

    float *x0, *qkv, *ctx, *tmp, *xmid, *ff;
    cudaGetSymbolAddress((void**)&x0,   g_x0);
    cudaGetSymbolAddress((void**)&qkv,  g_qkv);
    cudaGetSymbolAddress((void**)&ctx,  g_ctx);
    cudaGetSymbolAddress((void**)&tmp,  g_tmp);
    cudaGetSymbolAddress((void**)&xmid, g_xmid);
    cudaGetSymbolAddress((void**)&ff,   g_ff);

    cudaFuncSetAttribute(attn_kernel,
                         cudaFuncAttributeMaxDynamicSharedMemorySize, ATTN_SMEM);

    const int mtiles = (TOK + BM - 1) / BM;   // 17

    embed_kernel<<<dim3(S_LEN, BATCH), 256>>>(
        clip_embed, clip_score, input_tokens,
        clip_in_w, score_in_w, in_embed, pos_emb, x0);

    for (int l = 0; l < NLAYER; l++) {
        const float* xin = (l == 0) ? x0 : (cache + (size_t)(l - 1) * TOK * DMODEL);

        // qkv = xin @ Wqkv^T + bqkv
        gemm_nt<<<dim3(3 * DMODEL / BN, mtiles), 256>>>(
            xin, Wqkv + (size_t)l * 3 * DMODEL * DMODEL, bqkv + (size_t)l * 3 * DMODEL,
            qkv, TOK, 3 * DMODEL, DMODEL, 0);

        attn_kernel<<<BATCH * NHEAD, 256, ATTN_SMEM>>>(qkv, ctx);

        // a = ctx @ Wo^T + bo
        gemm_nt<<<dim3(DMODEL / BN, mtiles), 256>>>(
            ctx, Wo + (size_t)l * DMODEL * DMODEL, bo + (size_t)l * DMODEL,
            tmp, TOK, DMODEL, DMODEL, 0);

        // xmid = LN(xin + a)
        ln_res<<<TOK, 256>>>(xin, tmp, ln1_g + (size_t)l * DMODEL,
                             ln1_b + (size_t)l * DMODEL, xmid);

        // ff = gelu(xmid @ W1^T + b1)
        gemm_nt<<<dim3(FFDIM / BN, mtiles), 256>>>(
            xmid, W1 + (size_t)l * FFDIM * DMODEL, b1 + (size_t)l * FFDIM,
            ff, TOK, FFDIM, DMODEL, 1);

        // tmp = ff @ W2^T + b2
        gemm_nt<<<dim3(DMODEL / BN, mtiles), 256>>>(
            ff, W2 + (size_t)l * DMODEL * FFDIM, b2 + (size_t)l * DMODEL,
            tmp, TOK, DMODEL, FFDIM, 0);

        // cache[l] = LN(xmid + tmp)   (layer output, feeds next layer + head)
        ln_res<<<TOK, 256>>>(xmid, tmp, ln2_g + (size_t)l * DMODEL,
                             ln2_b + (size_t)l * DMODEL,
                             cache + (size_t)l * TOK * DMODEL);
    }

    // logits = out[1:] @ out_w^T + out_b, stored as [B, S-1, V]
    const float* xf = cache + (size_t)(NLAYER - 1) * TOK * DMODEL + BATCH * DMODEL;
    gemm_nt<<<dim3(VOCAB / BN, (SEQ_OUT * BATCH) / BM), 256>>>(
        xf, out_w, out_b, outp, SEQ_OUT * BATCH, VOCAB, DMODEL, 2);
}

// round 16
// speedup vs baseline: 1.3892x; 1.3892x over previous
#include <cuda_runtime.h>
#include <math.h>
#include <stdint.h>

// ---------------- problem constants ----------------
#define S_LEN   257
#define BATCH   8
#define TOK     (S_LEN * BATCH)      // 2056
#define DMODEL  1024
#define NHEAD   16
#define DHEAD   64
#define FFDIM   4096
#define NLAYER  24
#define VOCAB   16384
#define CLIPD   512
#define SEQ_OUT 256
#define LOGITS_ELEMS ((size_t)BATCH * SEQ_OUT * VOCAB)

// ---------------- scratch ----------------
__device__ float g_x0  [TOK * DMODEL];
__device__ float g_qkv [TOK * 3 * DMODEL];
__device__ float g_ctx [TOK * DMODEL];
__device__ float g_tmp [TOK * DMODEL];
__device__ float g_xmid[TOK * DMODEL];
__device__ float g_ff  [TOK * FFDIM];

// ---------------- 3xTF32 mma.sync GEMM: C = A[M,K] @ B[N,K]^T + bias ----------------
// Split precision: a = hi + lo (tf32 each); a*b = hi*hi + hi*lo + lo*hi (fp32-class).
// mode 0: plain   mode 1: exact gelu   mode 2: logits store (transpose to [B,S-1,V])
// CTA tile 128 x BN, BK=32, 3-stage cp.async. 8 warps: 2(M) x 4(N), warp tile 64 x WN.

#define NST 3
#define AST 36                                   // 32+4 pad: (36r+c)%32 = (4r+c)%32

#define CVT_TF32(u, f)  asm("cvt.rna.tf32.f32 %0, %1;" : "=r"(u) : "f"(f))

__device__ __forceinline__ void mma_tf32(float* d, const uint32_t* a,
                                         uint32_t b0, uint32_t b1) {
    asm volatile(
        "mma.sync.aligned.m16n8k8.row.col.f32.tf32.tf32.f32 "
        "{%0,%1,%2,%3}, {%4,%5,%6,%7}, {%8,%9}, {%0,%1,%2,%3};"
        : "+f"(d[0]), "+f"(d[1]), "+f"(d[2]), "+f"(d[3])
        : "r"(a[0]), "r"(a[1]), "r"(a[2]), "r"(a[3]), "r"(b0), "r"(b1));
}

template<int BN, int WN>
__global__ __launch_bounds__(256, 1) void gemm_tc(
    const float* __restrict__ A, const float* __restrict__ B,
    const float* __restrict__ bias, float* __restrict__ C,
    int M, int N, int K, int mode)
{
    constexpr int NF = WN / 8;                   // n-fragments per warp
    constexpr int STG = (128 + BN) * AST;        // floats per stage

    extern __shared__ __align__(16) float sm[];
    const uint32_t smem_u32 = (uint32_t)__cvta_generic_to_shared(sm);

    const int tid  = threadIdx.x;
    const int wid  = tid >> 5;
    const int lane = tid & 31;
    const int wm   = wid & 1;
    const int wn   = wid >> 1;
    const int r    = lane >> 2;
    const int c    = lane & 3;
    const int mBase = blockIdx.y * 128;
    const int nBase = blockIdx.x * BN;
    const int nb = K >> 5;

    float acc[4][NF][4];
#pragma unroll
    for (int i = 0; i < 4; i++)
#pragma unroll
        for (int j = 0; j < NF; j++)
#pragma unroll
            for (int q = 0; q < 4; q++) acc[i][j][q] = 0.f;

    auto load_stage = [&](int s, int kb) {
        const uint32_t base = smem_u32 + (uint32_t)(s * STG) * 4u;
        const float* Ak = A + (size_t)kb * 32;
        const float* Bk = B + (size_t)kb * 32;
        constexpr int NCHUNK = (128 + BN) * 8;
#pragma unroll
        for (int i = tid; i < NCHUNK; i += 256) {
            int row = i >> 3;
            int c8  = i & 7;
            uint32_t off = base + (uint32_t)(row * AST + c8 * 4) * 4u;
            const float* gp;
            if (row < 128) {
                int gr = mBase + row; gr = (gr < M) ? gr : (M - 1);
                gp = Ak + (size_t)gr * K + c8 * 4;
            } else {
                gp = Bk + (size_t)(nBase + row - 128) * K + c8 * 4;
            }
            asm volatile("cp.async.cg.shared.global [%0], [%1], 16;"
                         :: "r"(off), "l"(gp));
        }
    };

    // prologue: stages 0,1 hold k-blocks 0,1
    load_stage(0, 0);
    asm volatile("cp.async.commit_group;" ::: "memory");
    load_stage(1, 1);
    asm volatile("cp.async.commit_group;" ::: "memory");

    int st = 0, pf_st = 2;
    for (int kt = 0; kt < nb; kt++) {
        const int pf = kt + 2;
        if (pf < nb) load_stage(pf_st, pf);
        asm volatile("cp.async.commit_group;" ::: "memory");
        asm volatile("cp.async.wait_group %0;" :: "n"(2) : "memory");
        __syncthreads();

        const float* As = sm + st * STG + wm * 64 * AST;
        const float* Bs = sm + st * STG + 128 * AST + wn * WN * AST;

#pragma unroll
        for (int k8 = 0; k8 < 4; k8++) {
            const int kc = k8 * 8 + c;
            uint32_t uah[4][4], ual[4][4];
#pragma unroll
            for (int mf = 0; mf < 4; mf++) {
                float a0 = As[(mf * 16 + r) * AST + kc];
                float a1 = As[(mf * 16 + r + 8) * AST + kc];
                float a2 = As[(mf * 16 + r) * AST + kc + 4];
                float a3 = As[(mf * 16 + r + 8) * AST + kc + 4];
                CVT_TF32(uah[mf][0], a0); CVT_TF32(uah[mf][1], a1);
                CVT_TF32(uah[mf][2], a2); CVT_TF32(uah[mf][3], a3);
                float l0 = a0 - __uint_as_float(uah[mf][0]);
                float l1 = a1 - __uint_as_float(uah[mf][1]);
                float l2 = a2 - __uint_as_float(uah[mf][2]);
                float l3 = a3 - __uint_as_float(uah[mf][3]);
                CVT_TF32(ual[mf][0], l0); CVT_TF32(ual[mf][1], l1);
                CVT_TF32(ual[mf][2], l2); CVT_TF32(ual[mf][3], l3);
            }
#pragma unroll
            for (int nf = 0; nf < NF; nf++) {
                float b0 = Bs[(nf * 8 + r) * AST + kc];
                float b1 = Bs[(nf * 8 + r) * AST + kc + 4];
                uint32_t bh0, bh1, bl0, bl1;
                CVT_TF32(bh0, b0); CVT_TF32(bh1, b1);
                float l0 = b0 - __uint_as_float(bh0);
                float l1 = b1 - __uint_as_float(bh1);
                CVT_TF32(bl0, l0); CVT_TF32(bl1, l1);
#pragma unroll
                for (int mf = 0; mf < 4; mf++) {
                    mma_tf32(acc[mf][nf], uah[mf], bh0, bh1);   // hi*hi
                    mma_tf32(acc[mf][nf], uah[mf], bl0, bl1);   // hi*lo
                    mma_tf32(acc[mf][nf], ual[mf], bh0, bh1);   // lo*hi
                }
            }
        }
        __syncthreads();
        // FIX (R15 bug): rotate stages in order 0->1->2->0; consume st, prefetch pf_st
        st    = (st    + 1 == NST) ? 0 : (st    + 1);
        pf_st = (pf_st + 1 == NST) ? 0 : (pf_st + 1);
    }

    // ---- epilogue: bias (+gelu), float2 stores ----
#pragma unroll
    for (int mf = 0; mf < 4; mf++) {
        const int r0 = mBase + wm * 64 + mf * 16 + r;
        const int r1 = r0 + 8;
#pragma unroll
        for (int nf = 0; nf < NF; nf++) {
            const int col = nBase + wn * WN + nf * 8 + 2 * c;
            float2 bb = *(const float2*)(bias + col);
            float v0 = acc[mf][nf][0] + bb.x;
            float v1 = acc[mf][nf][1] + bb.y;
            float v2 = acc[mf][nf][2] + bb.x;
            float v3 = acc[mf][nf][3] + bb.y;
            if (mode == 1) {
                v0 = 0.5f * v0 * (1.0f + erff(v0 * 0.70710678118654752f));
                v1 = 0.5f * v1 * (1.0f + erff(v1 * 0.70710678118654752f));
                v2 = 0.5f * v2 * (1.0f + erff(v2 * 0.70710678118654752f));
                v3 = 0.5f * v3 * (1.0f + erff(v3 * 0.70710678118654752f));
            }
            if (mode == 2) {
                if (r0 < M)
                    *(float2*)(C + (size_t)(r0 & 7) * ((size_t)SEQ_OUT * VOCAB)
                                 + (size_t)(r0 >> 3) * VOCAB + col) = make_float2(v0, v1);
                if (r1 < M)
                    *(float2*)(C + (size_t)(r1 & 7) * ((size_t)SEQ_OUT * VOCAB)
                                 + (size_t)(r1 >> 3) * VOCAB + col) = make_float2(v2, v3);
            } else {
                if (r0 < M) *(float2*)(C + (size_t)r0 * N + col) = make_float2(v0, v1);
                if (r1 < M) *(float2*)(C + (size_t)r1 * N + col) = make_float2(v2, v3);
            }
        }
    }
}

#define SMEM_OF(BN) (NST * (128 + (BN)) * AST * 4)

// ---------------- residual + LayerNorm ----------------
__global__ __launch_bounds__(256) void ln_res(
    const float* __restrict__ x, const float* __restrict__ a,
    const float* __restrict__ g, const float* __restrict__ bt,
    float* __restrict__ out)
{
    const int t = blockIdx.x;
    const int i = threadIdx.x;
    const float4* x4 = (const float4*)(x + (size_t)t * DMODEL);
    const float4* a4 = (const float4*)(a + (size_t)t * DMODEL);
    float4 v = x4[i], av = a4[i];
    v.x += av.x; v.y += av.y; v.z += av.z; v.w += av.w;
    float s = v.x + v.y + v.z + v.w;
    float q = v.x * v.x + v.y * v.y + v.z * v.z + v.w * v.w;

    __shared__ float shs[8], shq[8];
    const int lane = i & 31, w = i >> 5;
#pragma unroll
    for (int o = 16; o; o >>= 1) {
        s += __shfl_xor_sync(0xffffffffu, s, o);
        q += __shfl_xor_sync(0xffffffffu, q, o);
    }
    if (lane == 0) { shs[w] = s; shq[w] = q; }
    __syncthreads();
    if (i < 32) {
        s = (lane < 8) ? shs[lane] : 0.f;
        q = (lane < 8) ? shq[lane] : 0.f;
#pragma unroll
        for (int o = 4; o; o >>= 1) {
            s += __shfl_xor_sync(0xffffffffu, s, o);
            q += __shfl_xor_sync(0xffffffffu, q, o);
        }
        if (lane == 0) { shs[0] = s; shq[0] = q; }
    }
    __syncthreads();
    const float mean = shs[0] * (1.0f / DMODEL);
    const float var  = shq[0] * (1.0f / DMODEL) - mean * mean;
    const float rstd = rsqrtf(var + 1e-5f);

    float4 g4 = ((const float4*)g)[i];
    float4 b4 = ((const float4*)bt)[i];
    float4 o4;
    o4.x = (v.x - mean) * rstd * g4.x + b4.x;
    o4.y = (v.y - mean) * rstd * g4.y + b4.y;
    o4.z = (v.z - mean) * rstd * g4.z + b4.z;
    o4.w = (v.w - mean) * rstd * g4.w + b4.w;
    ((float4*)(out + (size_t)t * DMODEL))[i] = o4;
}

// ---------------- attention ----------------
#define KVSTRIDE 68
#define ATTN_SMEM ((2 * S_LEN * KVSTRIDE + 8 * DHEAD + 8 * S_LEN) * 4)

__global__ __launch_bounds__(256) void attn_kernel(
    const float* __restrict__ qkv, float* __restrict__ ctx)
{
    extern __shared__ float smf[];
    float* Ks = smf;
    float* Vs = Ks + S_LEN * KVSTRIDE;
    float* Qs = Vs + S_LEN * KVSTRIDE;
    float* Pr = Qs + 8 * DHEAD;

    const int b = blockIdx.x >> 4;
    const int h = blockIdx.x & 15;
    const int tid = threadIdx.x;

    for (int i = tid; i < S_LEN * DHEAD; i += 256) {
        int s = i >> 6, d = i & 63;
        size_t base = (size_t)(s * BATCH + b) * (3 * DMODEL) + h * DHEAD + d;
        Ks[s * KVSTRIDE + d] = qkv[base + DMODEL];
        Vs[s * KVSTRIDE + d] = qkv[base + 2 * DMODEL];
    }
    __syncthreads();

    const int w = tid >> 5, lane = tid & 31;
    float* prw = Pr + w * S_LEN;
    const float4* qr = (const float4*)(Qs + w * DHEAD);

    for (int s = w; s < S_LEN; s += 8) {
        const float* qp = qkv + (size_t)(s * BATCH + b) * (3 * DMODEL) + h * DHEAD;
        Qs[w * DHEAD + lane]      = qp[lane];
        Qs[w * DHEAD + 32 + lane] = qp[32 + lane];
        __syncwarp();

        const int nt = (s == 0) ? 2 : (s + 1);   // mask quirk: [0,1] allowed

        float lmax = -1e30f;
        for (int t = lane; t < nt; t += 32) {
            const float4* kr = (const float4*)(Ks + t * KVSTRIDE);
            float sc = 0.f;
#pragma unroll
            for (int d4 = 0; d4 < 16; d4++) {
                float4 kv = kr[d4], qv = qr[d4];
                sc += qv.x * kv.x + qv.y * kv.y + qv.z * kv.z + qv.w * kv.w;
            }
            sc *= 0.125f;
            prw[t] = sc;
            lmax = fmaxf(lmax, sc);
        }
#pragma unroll
        for (int o = 16; o; o >>= 1)
            lmax = fmaxf(lmax, __shfl_xor_sync(0xffffffffu, lmax, o));

        float lsum = 0.f;
        for (int t = lane; t < nt; t += 32) {
            float p = expf(prw[t] - lmax);
            prw[t] = p;
            lsum += p;
        }
#pragma unroll
        for (int o = 16; o; o >>= 1)
            lsum += __shfl_xor_sync(0xffffffffu, lsum, o);
        __syncwarp();

        const float inv = 1.0f / lsum;
        float a0 = 0.f, a1 = 0.f;
        for (int t = 0; t < nt; t++) {
            float p = prw[t];
            a0 += p * Vs[t * KVSTRIDE + lane];
            a1 += p * Vs[t * KVSTRIDE + 32 + lane];
        }
        float* cp = ctx + (size_t)(s * BATCH + b) * DMODEL + h * DHEAD;
        cp[lane]      = a0 * inv;
        cp[32 + lane] = a1 * inv;
        __syncwarp();
    }
}

// ---------------- embedding ----------------
__global__ __launch_bounds__(256) void embed_kernel(
    const float* __restrict__ clip_embed, const float* __restrict__ clip_score,
    const int* __restrict__ tokens,
    const float* __restrict__ clip_in_w, const float* __restrict__ score_in_w,
    const float* __restrict__ in_embed, const float* __restrict__ pos_emb,
    float* __restrict__ x0)
{
    const int s = blockIdx.x;
    const int b = blockIdx.y;
    const int tid = threadIdx.x;
    float* outp = x0 + (size_t)(s * BATCH + b) * DMODEL;
    const float* pe = pos_emb + (size_t)s * DMODEL;

    if (s == 0) {
        __shared__ float ce[CLIPD];
        __shared__ float red[8];
        float ss = 0.f;
        for (int i = tid; i < CLIPD; i += 256) {
            float vv = clip_embed[b * CLIPD + i];
            ce[i] = vv;
            ss += vv * vv;
        }
        const int lane = tid & 31, w = tid >> 5;
#pragma unroll
        for (int o = 16; o; o >>= 1) ss += __shfl_xor_sync(0xffffffffu, ss, o);
        if (lane == 0) red[w] = ss;
        __syncthreads();
        if (tid == 0) {
            float tot = 0.f;
            for (int k = 0; k < 8; k++) tot += red[k];
            red[0] = tot;
        }
        __syncthreads();
        const float scale = sqrtf((float)CLIPD) / fmaxf(sqrtf(red[0]), 1e-12f);
        for (int d = tid; d < DMODEL; d += 256) {
            const float* wr = clip_in_w + (size_t)d * CLIPD;
            float acc = 0.f;
#pragma unroll 4
            for (int cc = 0; cc < CLIPD; cc++) acc += ce[cc] * wr[cc];
            outp[d] = acc * scale + pe[d];
        }
    } else if (s == 1) {
        const float cs = clip_score[b];
        for (int d = tid; d < DMODEL; d += 256)
            outp[d] = cs * score_in_w[d] + pe[d];
    } else {
        const int tk = tokens[b * (S_LEN - 2) + (s - 2)];
        const float* er = in_embed + (size_t)tk * DMODEL;
        for (int d = tid; d < DMODEL; d += 256)
            outp[d] = er[d] + pe[d];
    }
}

// ---------------- host launcher ----------------
extern "C" void kernel_launch(void* const* d_in, const int* in_sizes, int n_in,
                              void* d_out, int out_size)
{
    const float* clip_embed   = (const float*)d_in[0];
    const float* clip_score   = (const float*)d_in[1];
    const int*   input_tokens = (const int*)  d_in[2];
    const float* clip_in_w    = (const float*)d_in[3];
    const float* score_in_w   = (const float*)d_in[4];
    const float* in_embed     = (const float*)d_in[5];
    const float* pos_emb      = (const float*)d_in[6];
    const float* Wqkv         = (const float*)d_in[7];
    const float* bqkv         = (const float*)d_in[8];
    const float* Wo           = (const float*)d_in[9];
    const float* bo           = (const float*)d_in[10];
    const float* W1           = (const float*)d_in[11];
    const float* b1           = (const float*)d_in[12];
    const float* W2           = (const float*)d_in[13];
    const float* b2           = (const float*)d_in[14];
    const float* ln1_g        = (const float*)d_in[15];
    const float* ln1_b        = (const float*)d_in[16];
    const float* ln2_g        = (const float*)d_in[17];
    const float* ln2_b        = (const float*)d_in[18];
    const float* out_w        = (const float*)d_in[19];
    const float* out_b        = (const float*)d_in[20];

    float* outp  = (float*)d_out;
    float* cache = outp + LOGITS_ELEMS;

    float *x0, *qkv, *ctx, *tmp, *xmid, *ff;
    cudaGetSymbolAddress((void**)&x0,   g_x0);
    cudaGetSymbolAddress((void**)&qkv,  g_qkv);
    cudaGetSymbolAddress((void**)&ctx,  g_ctx);
    cudaGetSymbolAddress((void**)&tmp,  g_tmp);
    cudaGetSymbolAddress((void**)&xmid, g_xmid);
    cudaGetSymbolAddress((void**)&ff,   g_ff);

    cudaFuncSetAttribute(attn_kernel,
                         cudaFuncAttributeMaxDynamicSharedMemorySize, ATTN_SMEM);
    cudaFuncSetAttribute(gemm_tc<256, 64>,
                         cudaFuncAttributeMaxDynamicSharedMemorySize, SMEM_OF(256));
    cudaFuncSetAttribute(gemm_tc<128, 32>,
                         cudaFuncAttributeMaxDynamicSharedMemorySize, SMEM_OF(128));

    const int mtiles = (TOK + 127) / 128;   // 17

    embed_kernel<<<dim3(S_LEN, BATCH), 256>>>(
        clip_embed, clip_score, input_tokens,
        clip_in_w, score_in_w, in_embed, pos_emb, x0);

    for (int l = 0; l < NLAYER; l++) {
        const float* xin = (l == 0) ? x0 : (cache + (size_t)(l - 1) * TOK * DMODEL);

        gemm_tc<256, 64><<<dim3(3 * DMODEL / 256, mtiles), 256, SMEM_OF(256)>>>(
            xin, Wqkv + (size_t)l * 3 * DMODEL * DMODEL,
            bqkv + (size_t)l * 3 * DMODEL, qkv, TOK, 3 * DMODEL, DMODEL, 0);

        attn_kernel<<<BATCH * NHEAD, 256, ATTN_SMEM>>>(qkv, ctx);

        gemm_tc<128, 32><<<dim3(DMODEL / 128, mtiles), 256, SMEM_OF(128)>>>(
            ctx, Wo + (size_t)l * DMODEL * DMODEL, bo + (size_t)l * DMODEL,
            tmp, TOK, DMODEL, DMODEL, 0);

        ln_res<<<TOK, 256>>>(xin, tmp, ln1_g + (size_t)l * DMODEL,
                             ln1_b + (size_t)l * DMODEL, xmid);

        gemm_tc<256, 64><<<dim3(FFDIM / 256, mtiles), 256, SMEM_OF(256)>>>(
            xmid, W1 + (size_t)l * FFDIM * DMODEL, b1 + (size_t)l * FFDIM,
            ff, TOK, FFDIM, DMODEL, 1);

        gemm_tc<128, 32><<<dim3(DMODEL / 128, mtiles), 256, SMEM_OF(128)>>>(
            ff, W2 + (size_t)l * DMODEL * FFDIM, b2 + (size_t)l * DMODEL,
            tmp, TOK, DMODEL, FFDIM, 0);

        ln_res<<<TOK, 256>>>(xmid, tmp, ln2_g + (size_t)l * DMODEL,
                             ln2_b + (size_t)l * DMODEL,
                             cache + (size_t)l * TOK * DMODEL);
    }

    const float* xf = cache + (size_t)(NLAYER - 1) * TOK * DMODEL + BATCH * DMODEL;
    gemm_tc<256, 64><<<dim3(VOCAB / 256, (SEQ_OUT * BATCH) / 128), 256, SMEM_OF(256)>>>(
        xf, out_w, out_b, outp, SEQ_OUT * BATCH, VOCAB, DMODEL, 2);
}

// round 17
// speedup vs baseline: 1.3990x; 1.0071x over previous
#include <cuda_runtime.h>
#include <math.h>
#include <stdint.h>

// ---------------- problem constants ----------------
#define S_LEN   257
#define BATCH   8
#define TOK     (S_LEN * BATCH)      // 2056
#define DMODEL  1024
#define NHEAD   16
#define DHEAD   64
#define FFDIM   4096
#define NLAYER  24
#define VOCAB   16384
#define CLIPD   512
#define SEQ_OUT 256
#define LOGITS_ELEMS ((size_t)BATCH * SEQ_OUT * VOCAB)

#define WQKV_N (NLAYER * 3 * DMODEL * DMODEL)   // 75,497,472
#define WO_N   (NLAYER * DMODEL * DMODEL)       // 25,165,824
#define W1_N   (NLAYER * FFDIM * DMODEL)        // 100,663,296
#define W2_N   (NLAYER * DMODEL * FFDIM)        // 100,663,296
#define OW_N   (VOCAB * DMODEL)                 // 16,777,216

// ---------------- scratch ----------------
__device__ float g_x0  [TOK * DMODEL];
__device__ float g_qkv [TOK * 3 * DMODEL];
__device__ float g_tmp [TOK * DMODEL];
__device__ float g_xmid[TOK * DMODEL];
// activation hi/lo (tf32-valued fp32)
__device__ float g_xc_h [TOK * DMODEL], g_xc_l [TOK * DMODEL];
__device__ float g_ctx_h[TOK * DMODEL], g_ctx_l[TOK * DMODEL];
__device__ float g_xm_h [TOK * DMODEL], g_xm_l [TOK * DMODEL];
__device__ float g_ff_h [TOK * FFDIM],  g_ff_l [TOK * FFDIM];
// weight hi/lo
__device__ float g_wqkv_h[WQKV_N], g_wqkv_l[WQKV_N];
__device__ float g_wo_h  [WO_N],   g_wo_l  [WO_N];
__device__ float g_w1_h  [W1_N],   g_w1_l  [W1_N];
__device__ float g_w2_h  [W2_N],   g_w2_l  [W2_N];
__device__ float g_ow_h  [OW_N],   g_ow_l  [OW_N];

#define CVT_TF32(u, f)  asm("cvt.rna.tf32.f32 %0, %1;" : "=r"(u) : "f"(f))

__device__ __forceinline__ void hl_split(float v, float& h, float& l) {
    uint32_t uh; CVT_TF32(uh, v); h = __uint_as_float(uh);
    uint32_t ul; CVT_TF32(ul, v - h); l = __uint_as_float(ul);
}

// ---------------- weight hi/lo conversion (runs every call; ~0.8ms) ----------------
__global__ __launch_bounds__(256) void cvt_hl(
    const float4* __restrict__ w, float4* __restrict__ h,
    float4* __restrict__ l, int n4)
{
    int stride = gridDim.x * blockDim.x;
    for (int i = blockIdx.x * blockDim.x + threadIdx.x; i < n4; i += stride) {
        float4 v = w[i];
        float4 hh, ll;
        hl_split(v.x, hh.x, ll.x);
        hl_split(v.y, hh.y, ll.y);
        hl_split(v.z, hh.z, ll.z);
        hl_split(v.w, hh.w, ll.w);
        h[i] = hh; l[i] = ll;
    }
}

// ---------------- 3xTF32 GEMM, precomputed hi/lo operands ----------------
// C[M,N] = A[M,K] @ B[N,K]^T + bias.  a*b = ah*bh + ah*bl + al*bh.
// CTA 128x128, BK=32, NST=3 cp.async. 8 warps: 2(M) x 4(N), warp tile 64x32.
// smem row (per A/B row): [hi 32 floats | lo 32 floats | pad 4] = 68 words.
// mode 0: plain fp32    mode 1: gelu -> hi/lo only    mode 2: logits transpose

#define NST  3
#define ROWW 68
#define STGW (256 * ROWW)
#define GEMM_SMEM (NST * STGW * 4)   // 208,896 B

__device__ __forceinline__ void mma_tf32(float* d, const uint32_t* a,
                                         uint32_t b0, uint32_t b1) {
    asm volatile(
        "mma.sync.aligned.m16n8k8.row.col.f32.tf32.tf32.f32 "
        "{%0,%1,%2,%3}, {%4,%5,%6,%7}, {%8,%9}, {%0,%1,%2,%3};"
        : "+f"(d[0]), "+f"(d[1]), "+f"(d[2]), "+f"(d[3])
        : "r"(a[0]), "r"(a[1]), "r"(a[2]), "r"(a[3]), "r"(b0), "r"(b1));
}

__global__ __launch_bounds__(256, 1) void gemm3t(
    const float* __restrict__ Ah, const float* __restrict__ Al,
    const float* __restrict__ Bh, const float* __restrict__ Bl,
    const float* __restrict__ bias, float* __restrict__ C,
    float* __restrict__ Oh, float* __restrict__ Ol,
    int M, int N, int K, int mode)
{
    extern __shared__ __align__(16) uint32_t smw[];
    const uint32_t smem_u32 = (uint32_t)__cvta_generic_to_shared(smw);

    const int tid  = threadIdx.x;
    const int wid  = tid >> 5;
    const int lane = tid & 31;
    const int wm   = wid & 1;
    const int wn   = wid >> 1;
    const int r    = lane >> 2;
    const int c    = lane & 3;
    const int mBase = blockIdx.y * 128;
    const int nBase = blockIdx.x * 128;
    const int nb = K >> 5;

    float acc[4][4][4];
#pragma unroll
    for (int i = 0; i < 4; i++)
#pragma unroll
        for (int j = 0; j < 4; j++)
#pragma unroll
            for (int q = 0; q < 4; q++) acc[i][j][q] = 0.f;

    // 4096 16B-chunks per stage: row = i>>4, part = i&15 (0-7 hi, 8-15 lo)
    auto load_stage = [&](int s, int kb) {
        const uint32_t base = smem_u32 + (uint32_t)(s * STGW) * 4u;
#pragma unroll
        for (int j = 0; j < 16; j++) {
            int i   = tid + j * 256;
            int row = i >> 4;
            int part = i & 15;
            uint32_t dst = base + (uint32_t)(row * ROWW + part * 4) * 4u;
            int kOff = kb * 32 + (part & 7) * 4;
            const float* src;
            if (row < 128) {
                int gr = mBase + row; gr = (gr < M) ? gr : (M - 1);
                src = ((part < 8) ? Ah : Al) + (size_t)gr * K + kOff;
            } else {
                src = ((part < 8) ? Bh : Bl) + (size_t)(nBase + row - 128) * K + kOff;
            }
            asm volatile("cp.async.cg.shared.global [%0], [%1], 16;"
                         :: "r"(dst), "l"(src));
        }
    };

    load_stage(0, 0);
    asm volatile("cp.async.commit_group;" ::: "memory");
    load_stage(1, 1);
    asm volatile("cp.async.commit_group;" ::: "memory");

    int st = 0, pf_st = 2;
    for (int kt = 0; kt < nb; kt++) {
        const int pf = kt + 2;
        if (pf < nb) load_stage(pf_st, pf);
        asm volatile("cp.async.commit_group;" ::: "memory");
        asm volatile("cp.async.wait_group %0;" :: "n"(2) : "memory");
        __syncthreads();

        const uint32_t stW = (uint32_t)(st * STGW);
#pragma unroll
        for (int k8 = 0; k8 < 4; k8++) {
            const int kwo = k8 * 8 + c;
            uint32_t ah[4][4], alr[4][4], bh[4][2], blr[4][2];
#pragma unroll
            for (int mf = 0; mf < 4; mf++) {
                uint32_t w0 = stW + (uint32_t)((wm * 64 + mf * 16 + r) * ROWW) + kwo;
                ah[mf][0]  = smw[w0];          ah[mf][1]  = smw[w0 + 8 * ROWW];
                ah[mf][2]  = smw[w0 + 4];      ah[mf][3]  = smw[w0 + 8 * ROWW + 4];
                alr[mf][0] = smw[w0 + 32];     alr[mf][1] = smw[w0 + 8 * ROWW + 32];
                alr[mf][2] = smw[w0 + 36];     alr[mf][3] = smw[w0 + 8 * ROWW + 36];
            }
#pragma unroll
            for (int nf = 0; nf < 4; nf++) {
                uint32_t w0 = stW + (uint32_t)((128 + wn * 32 + nf * 8 + r) * ROWW) + kwo;
                bh[nf][0]  = smw[w0];      bh[nf][1]  = smw[w0 + 4];
                blr[nf][0] = smw[w0 + 32]; blr[nf][1] = smw[w0 + 36];
            }
            // three term passes; 16 independent accs between reuses
#pragma unroll
            for (int nf = 0; nf < 4; nf++)
#pragma unroll
                for (int mf = 0; mf < 4; mf++)
                    mma_tf32(acc[mf][nf], ah[mf], bh[nf][0], bh[nf][1]);
#pragma unroll
            for (int nf = 0; nf < 4; nf++)
#pragma unroll
                for (int mf = 0; mf < 4; mf++)
                    mma_tf32(acc[mf][nf], ah[mf], blr[nf][0], blr[nf][1]);
#pragma unroll
            for (int nf = 0; nf < 4; nf++)
#pragma unroll
                for (int mf = 0; mf < 4; mf++)
                    mma_tf32(acc[mf][nf], alr[mf], bh[nf][0], bh[nf][1]);
        }
        __syncthreads();
        st    = (st    + 1 == NST) ? 0 : (st    + 1);
        pf_st = (pf_st + 1 == NST) ? 0 : (pf_st + 1);
    }

    // ---- epilogue ----
#pragma unroll
    for (int mf = 0; mf < 4; mf++) {
        const int r0 = mBase + wm * 64 + mf * 16 + r;
        const int r1 = r0 + 8;
#pragma unroll
        for (int nf = 0; nf < 4; nf++) {
            const int col = nBase + wn * 32 + nf * 8 + 2 * c;
            float2 bb = *(const float2*)(bias + col);
            float v0 = acc[mf][nf][0] + bb.x;
            float v1 = acc[mf][nf][1] + bb.y;
            float v2 = acc[mf][nf][2] + bb.x;
            float v3 = acc[mf][nf][3] + bb.y;
            if (mode == 1) {
                // exact gelu, then hi/lo-only store (ff feeds FF2's A operand)
                v0 = 0.5f * v0 * (1.0f + erff(v0 * 0.70710678118654752f));
                v1 = 0.5f * v1 * (1.0f + erff(v1 * 0.70710678118654752f));
                v2 = 0.5f * v2 * (1.0f + erff(v2 * 0.70710678118654752f));
                v3 = 0.5f * v3 * (1.0f + erff(v3 * 0.70710678118654752f));
                float h0, l0, h1, l1, h2, l2, h3, l3;
                hl_split(v0, h0, l0); hl_split(v1, h1, l1);
                hl_split(v2, h2, l2); hl_split(v3, h3, l3);
                if (r0 < M) {
                    *(float2*)(Oh + (size_t)r0 * N + col) = make_float2(h0, h1);
                    *(float2*)(Ol + (size_t)r0 * N + col) = make_float2(l0, l1);
                }
                if (r1 < M) {
                    *(float2*)(Oh + (size_t)r1 * N + col) = make_float2(h2, h3);
                    *(float2*)(Ol + (size_t)r1 * N + col) = make_float2(l2, l3);
                }
            } else if (mode == 2) {
                if (r0 < M)
                    *(float2*)(C + (size_t)(r0 & 7) * ((size_t)SEQ_OUT * VOCAB)
                                 + (size_t)(r0 >> 3) * VOCAB + col) = make_float2(v0, v1);
                if (r1 < M)
                    *(float2*)(C + (size_t)(r1 & 7) * ((size_t)SEQ_OUT * VOCAB)
                                 + (size_t)(r1 >> 3) * VOCAB + col) = make_float2(v2, v3);
            } else {
                if (r0 < M) *(float2*)(C + (size_t)r0 * N + col) = make_float2(v0, v1);
                if (r1 < M) *(float2*)(C + (size_t)r1 * N + col) = make_float2(v2, v3);
            }
        }
    }
}

// ---------------- residual + LayerNorm (+ hi/lo emit) ----------------
__global__ __launch_bounds__(256) void ln_res(
    const float* __restrict__ x, const float* __restrict__ a,
    const float* __restrict__ g, const float* __restrict__ bt,
    float* __restrict__ out, float* __restrict__ oh, float* __restrict__ ol)
{
    const int t = blockIdx.x;
    const int i = threadIdx.x;
    const float4* x4 = (const float4*)(x + (size_t)t * DMODEL);
    const float4* a4 = (const float4*)(a + (size_t)t * DMODEL);
    float4 v = x4[i], av = a4[i];
    v.x += av.x; v.y += av.y; v.z += av.z; v.w += av.w;
    float s = v.x + v.y + v.z + v.w;
    float q = v.x * v.x + v.y * v.y + v.z * v.z + v.w * v.w;

    __shared__ float shs[8], shq[8];
    const int lane = i & 31, w = i >> 5;
#pragma unroll
    for (int o = 16; o; o >>= 1) {
        s += __shfl_xor_sync(0xffffffffu, s, o);
        q += __shfl_xor_sync(0xffffffffu, q, o);
    }
    if (lane == 0) { shs[w] = s; shq[w] = q; }
    __syncthreads();
    if (i < 32) {
        s = (lane < 8) ? shs[lane] : 0.f;
        q = (lane < 8) ? shq[lane] : 0.f;
#pragma unroll
        for (int o = 4; o; o >>= 1) {
            s += __shfl_xor_sync(0xffffffffu, s, o);
            q += __shfl_xor_sync(0xffffffffu, q, o);
        }
        if (lane == 0) { shs[0] = s; shq[0] = q; }
    }
    __syncthreads();
    const float mean = shs[0] * (1.0f / DMODEL);
    const float var  = shq[0] * (1.0f / DMODEL) - mean * mean;
    const float rstd = rsqrtf(var + 1e-5f);

    float4 g4 = ((const float4*)g)[i];
    float4 b4 = ((const float4*)bt)[i];
    float4 o4;
    o4.x = (v.x - mean) * rstd * g4.x + b4.x;
    o4.y = (v.y - mean) * rstd * g4.y + b4.y;
    o4.z = (v.z - mean) * rstd * g4.z + b4.z;
    o4.w = (v.w - mean) * rstd * g4.w + b4.w;
    ((float4*)(out + (size_t)t * DMODEL))[i] = o4;

    float4 hh, ll;
    hl_split(o4.x, hh.x, ll.x);
    hl_split(o4.y, hh.y, ll.y);
    hl_split(o4.z, hh.z, ll.z);
    hl_split(o4.w, hh.w, ll.w);
    ((float4*)(oh + (size_t)t * DMODEL))[i] = hh;
    ((float4*)(ol + (size_t)t * DMODEL))[i] = ll;
}

// ---------------- attention (ctx emitted as hi/lo) ----------------
#define KVSTRIDE 68
#define ATTN_SMEM ((2 * S_LEN * KVSTRIDE + 8 * DHEAD + 8 * S_LEN) * 4)

__global__ __launch_bounds__(256) void attn_kernel(
    const float* __restrict__ qkv,
    float* __restrict__ ctx_h, float* __restrict__ ctx_l)
{
    extern __shared__ float smf[];
    float* Ks = smf;
    float* Vs = Ks + S_LEN * KVSTRIDE;
    float* Qs = Vs + S_LEN * KVSTRIDE;
    float* Pr = Qs + 8 * DHEAD;

    const int b = blockIdx.x >> 4;
    const int h = blockIdx.x & 15;
    const int tid = threadIdx.x;

    for (int i = tid; i < S_LEN * DHEAD; i += 256) {
        int s = i >> 6, d = i & 63;
        size_t base = (size_t)(s * BATCH + b) * (3 * DMODEL) + h * DHEAD + d;
        Ks[s * KVSTRIDE + d] = qkv[base + DMODEL];
        Vs[s * KVSTRIDE + d] = qkv[base + 2 * DMODEL];
    }
    __syncthreads();

    const int w = tid >> 5, lane = tid & 31;
    float* prw = Pr + w * S_LEN;
    const float4* qr = (const float4*)(Qs + w * DHEAD);

    for (int s = w; s < S_LEN; s += 8) {
        const float* qp = qkv + (size_t)(s * BATCH + b) * (3 * DMODEL) + h * DHEAD;
        Qs[w * DHEAD + lane]      = qp[lane];
        Qs[w * DHEAD + 32 + lane] = qp[32 + lane];
        __syncwarp();

        const int nt = (s == 0) ? 2 : (s + 1);   // mask quirk: [0,1] allowed

        float lmax = -1e30f;
        for (int t = lane; t < nt; t += 32) {
            const float4* kr = (const float4*)(Ks + t * KVSTRIDE);
            float sc = 0.f;
#pragma unroll
            for (int d4 = 0; d4 < 16; d4++) {
                float4 kv = kr[d4], qv = qr[d4];
                sc += qv.x * kv.x + qv.y * kv.y + qv.z * kv.z + qv.w * kv.w;
            }
            sc *= 0.125f;
            prw[t] = sc;
            lmax = fmaxf(lmax, sc);
        }
#pragma unroll
        for (int o = 16; o; o >>= 1)
            lmax = fmaxf(lmax, __shfl_xor_sync(0xffffffffu, lmax, o));

        float lsum = 0.f;
        for (int t = lane; t < nt; t += 32) {
            float p = expf(prw[t] - lmax);
            prw[t] = p;
            lsum += p;
        }
#pragma unroll
        for (int o = 16; o; o >>= 1)
            lsum += __shfl_xor_sync(0xffffffffu, lsum, o);
        __syncwarp();

        const float inv = 1.0f / lsum;
        float a0 = 0.f, a1 = 0.f;
        for (int t = 0; t < nt; t++) {
            float p = prw[t];
            a0 += p * Vs[t * KVSTRIDE + lane];
            a1 += p * Vs[t * KVSTRIDE + 32 + lane];
        }
        size_t idx = (size_t)(s * BATCH + b) * DMODEL + h * DHEAD;
        float h0, l0, h1, l1;
        hl_split(a0 * inv, h0, l0);
        hl_split(a1 * inv, h1, l1);
        ctx_h[idx + lane]      = h0; ctx_l[idx + lane]      = l0;
        ctx_h[idx + 32 + lane] = h1; ctx_l[idx + 32 + lane] = l1;
        __syncwarp();
    }
}

// ---------------- embedding (x0 fp32 + hi/lo) ----------------
__global__ __launch_bounds__(256) void embed_kernel(
    const float* __restrict__ clip_embed, const float* __restrict__ clip_score,
    const int* __restrict__ tokens,
    const float* __restrict__ clip_in_w, const float* __restrict__ score_in_w,
    const float* __restrict__ in_embed, const float* __restrict__ pos_emb,
    float* __restrict__ x0, float* __restrict__ xh, float* __restrict__ xl)
{
    const int s = blockIdx.x;
    const int b = blockIdx.y;
    const int tid = threadIdx.x;
    const size_t rowo = (size_t)(s * BATCH + b) * DMODEL;
    const float* pe = pos_emb + (size_t)s * DMODEL;

    if (s == 0) {
        __shared__ float ce[CLIPD];
        __shared__ float red[8];
        float ss = 0.f;
        for (int i = tid; i < CLIPD; i += 256) {
            float vv = clip_embed[b * CLIPD + i];
            ce[i] = vv;
            ss += vv * vv;
        }
        const int lane = tid & 31, w = tid >> 5;
#pragma unroll
        for (int o = 16; o; o >>= 1) ss += __shfl_xor_sync(0xffffffffu, ss, o);
        if (lane == 0) red[w] = ss;
        __syncthreads();
        if (tid == 0) {
            float tot = 0.f;
            for (int k = 0; k < 8; k++) tot += red[k];
            red[0] = tot;
        }
        __syncthreads();
        const float scale = sqrtf((float)CLIPD) / fmaxf(sqrtf(red[0]), 1e-12f);
        for (int d = tid; d < DMODEL; d += 256) {
            const float* wr = clip_in_w + (size_t)d * CLIPD;
            float acc = 0.f;
#pragma unroll 4
            for (int cc = 0; cc < CLIPD; cc++) acc += ce[cc] * wr[cc];
            float v = acc * scale + pe[d];
            x0[rowo + d] = v;
            hl_split(v, xh[rowo + d], xl[rowo + d]);
        }
    } else if (s == 1) {
        const float cs = clip_score[b];
        for (int d = tid; d < DMODEL; d += 256) {
            float v = cs * score_in_w[d] + pe[d];
            x0[rowo + d] = v;
            hl_split(v, xh[rowo + d], xl[rowo + d]);
        }
    } else {
        const int tk = tokens[b * (S_LEN - 2) + (s - 2)];
        const float* er = in_embed + (size_t)tk * DMODEL;
        for (int d = tid; d < DMODEL; d += 256) {
            float v = er[d] + pe[d];
            x0[rowo + d] = v;
            hl_split(v, xh[rowo + d], xl[rowo + d]);
        }
    }
}

// ---------------- host launcher ----------------
extern "C" void kernel_launch(void* const* d_in, const int* in_sizes, int n_in,
                              void* d_out, int out_size)
{
    const float* clip_embed   = (const float*)d_in[0];
    const float* clip_score   = (const float*)d_in[1];
    const int*   input_tokens = (const int*)  d_in[2];
    const float* clip_in_w    = (const float*)d_in[3];
    const float* score_in_w   = (const float*)d_in[4];
    const float* in_embed     = (const float*)d_in[5];
    const float* pos_emb      = (const float*)d_in[6];
    const float* Wqkv         = (const float*)d_in[7];
    const float* bqkv         = (const float*)d_in[8];
    const float* Wo           = (const float*)d_in[9];
    const float* bo           = (const float*)d_in[10];
    const float* W1           = (const float*)d_in[11];
    const float* b1           = (const float*)d_in[12];
    const float* W2           = (const float*)d_in[13];
    const float* b2           = (const float*)d_in[14];
    const float* ln1_g        = (const float*)d_in[15];
    const float* ln1_b        = (const float*)d_in[16];
    const float* ln2_g        = (const float*)d_in[17];
    const float* ln2_b        = (const float*)d_in[18];
    const float* out_w        = (const float*)d_in[19];
    const float* out_b        = (const float*)d_in[20];

    float* outp  = (float*)d_out;
    float* cache = outp + LOGITS_ELEMS;

    float *x0, *qkv, *tmp, *xmid;
    float *xch, *xcl, *ctxh, *ctxl, *xmh, *xml, *ffh, *ffl;
    float *wqh, *wql, *woh, *wol, *w1h, *w1l, *w2h, *w2l, *owh, *owl;
    cudaGetSymbolAddress((void**)&x0,   g_x0);
    cudaGetSymbolAddress((void**)&qkv,  g_qkv);
    cudaGetSymbolAddress((void**)&tmp,  g_tmp);
    cudaGetSymbolAddress((void**)&xmid, g_xmid);
    cudaGetSymbolAddress((void**)&xch,  g_xc_h);  cudaGetSymbolAddress((void**)&xcl,  g_xc_l);
    cudaGetSymbolAddress((void**)&ctxh, g_ctx_h); cudaGetSymbolAddress((void**)&ctxl, g_ctx_l);
    cudaGetSymbolAddress((void**)&xmh,  g_xm_h);  cudaGetSymbolAddress((void**)&xml,  g_xm_l);
    cudaGetSymbolAddress((void**)&ffh,  g_ff_h);  cudaGetSymbolAddress((void**)&ffl,  g_ff_l);
    cudaGetSymbolAddress((void**)&wqh,  g_wqkv_h); cudaGetSymbolAddress((void**)&wql, g_wqkv_l);
    cudaGetSymbolAddress((void**)&woh,  g_wo_h);   cudaGetSymbolAddress((void**)&wol, g_wo_l);
    cudaGetSymbolAddress((void**)&w1h,  g_w1_h);   cudaGetSymbolAddress((void**)&w1l, g_w1_l);
    cudaGetSymbolAddress((void**)&w2h,  g_w2_h);   cudaGetSymbolAddress((void**)&w2l, g_w2_l);
    cudaGetSymbolAddress((void**)&owh,  g_ow_h);   cudaGetSymbolAddress((void**)&owl, g_ow_l);

    cudaFuncSetAttribute(attn_kernel,
                         cudaFuncAttributeMaxDynamicSharedMemorySize, ATTN_SMEM);
    cudaFuncSetAttribute(gemm3t,
                         cudaFuncAttributeMaxDynamicSharedMemorySize, GEMM_SMEM);

    // weight hi/lo precompute (same values the in-kernel split produced before)
    cvt_hl<<<4096, 256>>>((const float4*)Wqkv, (float4*)wqh, (float4*)wql, WQKV_N / 4);
    cvt_hl<<<4096, 256>>>((const float4*)Wo,   (float4*)woh, (float4*)wol, WO_N   / 4);
    cvt_hl<<<4096, 256>>>((const float4*)W1,   (float4*)w1h, (float4*)w1l, W1_N   / 4);
    cvt_hl<<<4096, 256>>>((const float4*)W2,   (float4*)w2h, (float4*)w2l, W2_N   / 4);
    cvt_hl<<<4096, 256>>>((const float4*)out_w,(float4*)owh, (float4*)owl, OW_N   / 4);

    const int mtiles = (TOK + 127) / 128;   // 17

    embed_kernel<<<dim3(S_LEN, BATCH), 256>>>(
        clip_embed, clip_score, input_tokens,
        clip_in_w, score_in_w, in_embed, pos_emb, x0, xch, xcl);

    for (int l = 0; l < NLAYER; l++) {
        const float* xin = (l == 0) ? x0 : (cache + (size_t)(l - 1) * TOK * DMODEL);

        // qkv = x @ Wqkv^T + bqkv
        gemm3t<<<dim3(3 * DMODEL / 128, mtiles), 256, GEMM_SMEM>>>(
            xch, xcl, wqh + (size_t)l * 3 * DMODEL * DMODEL,
            wql + (size_t)l * 3 * DMODEL * DMODEL,
            bqkv + (size_t)l * 3 * DMODEL, qkv, nullptr, nullptr,
            TOK, 3 * DMODEL, DMODEL, 0);

        attn_kernel<<<BATCH * NHEAD, 256, ATTN_SMEM>>>(qkv, ctxh, ctxl);

        // a = ctx @ Wo^T + bo
        gemm3t<<<dim3(DMODEL / 128, mtiles), 256, GEMM_SMEM>>>(
            ctxh, ctxl, woh + (size_t)l * DMODEL * DMODEL,
            wol + (size_t)l * DMODEL * DMODEL,
            bo + (size_t)l * DMODEL, tmp, nullptr, nullptr,
            TOK, DMODEL, DMODEL, 0);

        ln_res<<<TOK, 256>>>(xin, tmp, ln1_g + (size_t)l * DMODEL,
                             ln1_b + (size_t)l * DMODEL, xmid, xmh, xml);

        // ff = gelu(xmid @ W1^T + b1)  -> hi/lo only
        gemm3t<<<dim3(FFDIM / 128, mtiles), 256, GEMM_SMEM>>>(
            xmh, xml, w1h + (size_t)l * FFDIM * DMODEL,
            w1l + (size_t)l * FFDIM * DMODEL,
            b1 + (size_t)l * FFDIM, nullptr, ffh, ffl,
            TOK, FFDIM, DMODEL, 1);

        // tmp = ff @ W2^T + b2
        gemm3t<<<dim3(DMODEL / 128, mtiles), 256, GEMM_SMEM>>>(
            ffh, ffl, w2h + (size_t)l * DMODEL * FFDIM,
            w2l + (size_t)l * DMODEL * FFDIM,
            b2 + (size_t)l * DMODEL, tmp, nullptr, nullptr,
            TOK, DMODEL, FFDIM, 0);

        // cache[l] = LN(xmid + tmp); also emits next layer's A hi/lo
        ln_res<<<TOK, 256>>>(xmid, tmp, ln2_g + (size_t)l * DMODEL,
                             ln2_b + (size_t)l * DMODEL,
                             cache + (size_t)l * TOK * DMODEL, xch, xcl);
    }

    // logits = out[1:] @ out_w^T + out_b  (A = final-layer hi/lo, skip s=0 rows)
    gemm3t<<<dim3(VOCAB / 128, (SEQ_OUT * BATCH) / 128), 256, GEMM_SMEM>>>(
        xch + (size_t)BATCH * DMODEL, xcl + (size_t)BATCH * DMODEL,
        owh, owl, out_b, outp, nullptr, nullptr,
        SEQ_OUT * BATCH, VOCAB, DMODEL, 2);
}